// round 1
// baseline (speedup 1.0000x reference)
#include <cuda_runtime.h>
#include <math.h>

#define NN 50000
#define EE 800000
#define DIN 20
#define DD 128
#define BN_EPS 1e-5f
#define GEMM_SMEM (size_t)((128*129 + 128*64) * sizeof(float))

// ---------------- scratch (device globals; no runtime allocation) ----------
__device__ float g_h[NN * DD];     // layer activations
__device__ float g_k[NN * DD];     // k = h @ wk
__device__ float g_q[NN * DD];     // q = h @ wq
__device__ float g_v[NN * DD];     // v = h @ wv
__device__ float g_agg[NN * DD];   // skip + aggregated messages
__device__ float g_sum[DD], g_sumsq[DD], g_mean[DD], g_rstd[DD];
__device__ unsigned int g_or;      // OR of odd int32 words of edge row 0 (0 => int64)

// ---------------- edge-index dtype detection -------------------------------
__global__ void zero_or_kernel() { if (threadIdx.x == 0) g_or = 0u; }

__global__ void detect_kernel(const unsigned int* __restrict__ w) {
    // Reads only the first 2*EE int32 words (= first EE int64s), safe for both dtypes.
    unsigned int v = 0;
    for (long long i = blockIdx.x * (long long)blockDim.x + threadIdx.x;
         i < EE; i += (long long)gridDim.x * blockDim.x)
        v |= w[2 * i + 1];
#pragma unroll
    for (int o = 16; o > 0; o >>= 1) v |= __shfl_xor_sync(0xffffffffu, v, o);
    if ((threadIdx.x & 31) == 0 && v) atomicOr(&g_or, v);
}

// ---------------- pre-MP linear: g_h = x @ pre_w ---------------------------
__global__ void pre_linear_kernel(const float* __restrict__ x,
                                  const float* __restrict__ w) {
    __shared__ float ws[DIN * DD];
    for (int i = threadIdx.x; i < DIN * DD; i += blockDim.x) ws[i] = w[i];
    __syncthreads();
    int idx = blockIdx.x * blockDim.x + threadIdx.x;
    if (idx >= NN * DD) return;
    int row = idx >> 7;
    int c = idx & 127;
    const float* xr = x + (size_t)row * DIN;
    float acc = 0.f;
#pragma unroll
    for (int kk = 0; kk < DIN; kk++) acc += xr[kk] * ws[kk * DD + c];
    g_h[idx] = acc;
}

// ---------------- BatchNorm (training-mode) statistics ----------------------
__global__ void zero_stats_kernel() {
    g_sum[threadIdx.x] = 0.f;
    g_sumsq[threadIdx.x] = 0.f;
}

__global__ void bn_stats_kernel(int which) {
    const float* xp = which ? g_agg : g_h;
    int c = threadIdx.x;
    float s = 0.f, s2 = 0.f;
    for (int r = blockIdx.x; r < NN; r += gridDim.x) {
        float v = xp[(size_t)r * DD + c];
        s += v;
        s2 += v * v;
    }
    atomicAdd(&g_sum[c], s);
    atomicAdd(&g_sumsq[c], s2);
}

__global__ void bn_finalize_kernel() {
    int c = threadIdx.x;
    float mu = g_sum[c] * (1.f / NN);
    float var = g_sumsq[c] * (1.f / NN) - mu * mu;
    g_mean[c] = mu;
    g_rstd[c] = rsqrtf(var + BN_EPS);
}

// ---------------- fused BN -> ReLU -> l2norm (one warp per row) -------------
__global__ void bn_apply_kernel(int which, const float* __restrict__ gamma,
                                const float* __restrict__ beta,
                                float* __restrict__ out_ext) {
    const float* xp = which ? g_agg : g_h;
    int gt = blockIdx.x * blockDim.x + threadIdx.x;
    int row = gt >> 5;
    int lane = gt & 31;
    if (row >= NN) return;
    int c0 = lane * 4;
    float4 xv = *(const float4*)(xp + (size_t)row * DD + c0);
    float y[4];
    float xs[4] = {xv.x, xv.y, xv.z, xv.w};
    float ss = 0.f;
#pragma unroll
    for (int j = 0; j < 4; j++) {
        int c = c0 + j;
        float val = (xs[j] - g_mean[c]) * g_rstd[c] * gamma[c] + beta[c];
        val = fmaxf(val, 0.f);
        y[j] = val;
        ss += val * val;
    }
#pragma unroll
    for (int o = 16; o > 0; o >>= 1) ss += __shfl_xor_sync(0xffffffffu, ss, o);
    float sc = 1.f / fmaxf(sqrtf(ss), 1e-12f);
    float* op = out_ext ? out_ext : g_h;
    float4 ov = make_float4(y[0] * sc, y[1] * sc, y[2] * sc, y[3] * sc);
    *(float4*)(op + (size_t)row * DD + c0) = ov;
}

// ---------------- 4-way SGEMM: {k,q,v,skip} = g_h @ {wk,wq,wv,ws} -----------
// grid (8, ceil(NN/128)); blockIdx.x selects (matrix, 64-col half).
// Tile: 128 rows x 64 cols, K=128 single-stage. 256 threads, 8x4 microtile.
__global__ void gemm4_kernel(const float* __restrict__ wkp,
                             const float* __restrict__ wqp,
                             const float* __restrict__ wvp,
                             const float* __restrict__ wsp) {
    extern __shared__ float sm[];
    float* As = sm;             // [128][129]  (pad kills ty bank conflict)
    float* Bs = sm + 128 * 129; // [128][64]
    int t = threadIdx.x;
    int bx = blockIdx.x;
    int mat = bx >> 1;
    int col0 = (bx & 1) * 64;
    const float* W = (mat == 0) ? wkp : (mat == 1) ? wqp : (mat == 2) ? wvp : wsp;
    float* O = (mat == 0) ? g_k : (mat == 1) ? g_q : (mat == 2) ? g_v : g_agg;
    int row0 = blockIdx.y * 128;

    // Load A tile (float4, coalesced), zero-fill OOB rows.
    {
        int k4 = t & 31;  // float4 column
        int r0 = t >> 5;  // 0..7
#pragma unroll
        for (int rr = r0; rr < 128; rr += 8) {
            float4 val = make_float4(0.f, 0.f, 0.f, 0.f);
            int grow = row0 + rr;
            if (grow < NN) val = *(const float4*)(g_h + (size_t)grow * DD + k4 * 4);
            float* dst = As + rr * 129 + k4 * 4;
            dst[0] = val.x; dst[1] = val.y; dst[2] = val.z; dst[3] = val.w;
        }
    }
    // Load B tile (coalesced rows of 64).
    {
        int c = t & 63;
        int k0 = t >> 6;  // 0..3
#pragma unroll
        for (int kk = k0; kk < 128; kk += 4)
            Bs[kk * 64 + c] = W[kk * DD + col0 + c];
    }
    __syncthreads();

    int ty = t >> 4, tx = t & 15;
    float acc[8][4];
#pragma unroll
    for (int i = 0; i < 8; i++)
#pragma unroll
        for (int j = 0; j < 4; j++) acc[i][j] = 0.f;

    const float* arow = As + (ty * 8) * 129;
#pragma unroll 8
    for (int kk = 0; kk < 128; kk++) {
        float4 b = *(const float4*)(Bs + kk * 64 + tx * 4);
#pragma unroll
        for (int i = 0; i < 8; i++) {
            float a = arow[i * 129 + kk];
            acc[i][0] += a * b.x;
            acc[i][1] += a * b.y;
            acc[i][2] += a * b.z;
            acc[i][3] += a * b.w;
        }
    }

    int crow0 = row0 + ty * 8;
#pragma unroll
    for (int i = 0; i < 8; i++) {
        int grow = crow0 + i;
        if (grow < NN) {
            float4 ov = make_float4(acc[i][0], acc[i][1], acc[i][2], acc[i][3]);
            *(float4*)(O + (size_t)grow * DD + col0 + tx * 4) = ov;
        }
    }
}

// ---------------- edge message + scatter (one warp per edge) ----------------
__global__ void edge_kernel(const int* __restrict__ ei) {
    long long gt = blockIdx.x * (long long)blockDim.x + threadIdx.x;
    int e = (int)(gt >> 5);
    int lane = (int)(gt & 31);
    if (e >= EE) return;
    int s, d;
    if (g_or == 0u) {  // int64 edge_index
        const long long* e64 = (const long long*)ei;
        s = (int)e64[e];
        d = (int)e64[EE + e];
    } else {           // int32 edge_index
        s = __ldg(ei + e);
        d = __ldg(ei + EE + e);
    }
    size_t so = (size_t)s * DD + lane * 4;
    size_t dofs = (size_t)d * DD + lane * 4;
    float4 kk = *(const float4*)(g_k + dofs);
    float4 qq = *(const float4*)(g_q + so);
    float4 vv = *(const float4*)(g_v + so);
    float4 m;
    m.x = vv.x / (1.f + __expf(-(kk.x + qq.x)));
    m.y = vv.y / (1.f + __expf(-(kk.y + qq.y)));
    m.z = vv.z / (1.f + __expf(-(kk.z + qq.z)));
    m.w = vv.w / (1.f + __expf(-(kk.w + qq.w)));
    float* ap = g_agg + dofs;
    atomicAdd(ap + 0, m.x);
    atomicAdd(ap + 1, m.y);
    atomicAdd(ap + 2, m.z);
    atomicAdd(ap + 3, m.w);
}

// ---------------- launch ----------------------------------------------------
extern "C" void kernel_launch(void* const* d_in, const int* in_sizes, int n_in,
                              void* d_out, int out_size) {
    const float* x     = (const float*)d_in[0];
    const int*   ei    = (const int*)d_in[1];
    const float* pre_w = (const float*)d_in[2];
    const float* pre_g = (const float*)d_in[3];
    const float* pre_b = (const float*)d_in[4];
    const float* wk    = (const float*)d_in[5];
    const float* wq    = (const float*)d_in[6];
    const float* wv    = (const float*)d_in[7];
    const float* ws    = (const float*)d_in[8];
    const float* mg    = (const float*)d_in[9];
    const float* mb    = (const float*)d_in[10];
    float* outp = (float*)d_out;

    cudaFuncSetAttribute(gemm4_kernel,
                         cudaFuncAttributeMaxDynamicSharedMemorySize,
                         (int)GEMM_SMEM);

    // edge dtype detection (deterministic per input)
    zero_or_kernel<<<1, 32>>>();
    detect_kernel<<<256, 256>>>((const unsigned int*)ei);

    // pre-MP: linear -> BN -> ReLU -> l2norm
    pre_linear_kernel<<<(NN * DD + 255) / 256, 256>>>(x, pre_w);
    zero_stats_kernel<<<1, DD>>>();
    bn_stats_kernel<<<256, DD>>>(0);
    bn_finalize_kernel<<<1, DD>>>();
    bn_apply_kernel<<<(NN * 32 + 255) / 256, 256>>>(0, pre_g, pre_b, nullptr);

    const int gemm_gy = (NN + 127) / 128;
    for (int l = 0; l < 2; l++) {
        gemm4_kernel<<<dim3(8, gemm_gy), 256, GEMM_SMEM>>>(
            wk + l * DD * DD, wq + l * DD * DD, wv + l * DD * DD, ws + l * DD * DD);
        edge_kernel<<<(int)(((long long)EE * 32 + 255) / 256), 256>>>(ei);
        zero_stats_kernel<<<1, DD>>>();
        bn_stats_kernel<<<256, DD>>>(1);
        bn_finalize_kernel<<<1, DD>>>();
        bn_apply_kernel<<<(NN * 32 + 255) / 256, 256>>>(
            1, mg + l * DD, mb + l * DD, (l == 1) ? outp : nullptr);
    }
}

// round 2
// speedup vs baseline: 1.2867x; 1.2867x over previous
#include <cuda_runtime.h>
#include <math.h>

#define NN 50000
#define EE 800000
#define DIN 20
#define DD 128
#define BN_EPS 1e-5f

#define BPAD 132
#define GEMM_SMEM (size_t)((128 * 128 + 64 * BPAD) * sizeof(float))

typedef unsigned long long u64;

// ---------------- scratch (device globals; no runtime allocation) ----------
__device__ float g_h[NN * DD];
__device__ float g_k[NN * DD];
__device__ float g_q[NN * DD];
__device__ float g_v[NN * DD];
__device__ float g_agg[NN * DD];
__device__ float g_sum[3 * DD], g_sumsq[3 * DD];
__device__ unsigned int g_or;  // OR of odd int32 words of edge row 0 (0 => int64)

// ---------------- f32x2 helpers ---------------------------------------------
__device__ __forceinline__ void ffma2(u64& d, u64 a, u64 b) {
    asm("fma.rn.f32x2 %0, %1, %2, %3;" : "=l"(d) : "l"(a), "l"(b), "l"(d));
}
__device__ __forceinline__ float fold2(u64 v) {
    float lo, hi;
    asm("mov.b64 {%0,%1}, %2;" : "=f"(lo), "=f"(hi) : "l"(v));
    return lo + hi;
}

// ---------------- init: zero detection flag + all BN stat slots -------------
__global__ void init_kernel() {
    int t = threadIdx.x;
    if (t == 0) g_or = 0u;
    for (int i = t; i < 3 * DD; i += blockDim.x) {
        g_sum[i] = 0.f;
        g_sumsq[i] = 0.f;
    }
}

__global__ void detect_kernel(const unsigned int* __restrict__ w) {
    unsigned int v = 0;
    for (long long i = blockIdx.x * (long long)blockDim.x + threadIdx.x;
         i < EE; i += (long long)gridDim.x * blockDim.x)
        v |= w[2 * i + 1];
#pragma unroll
    for (int o = 16; o > 0; o >>= 1) v |= __shfl_xor_sync(0xffffffffu, v, o);
    if ((threadIdx.x & 31) == 0 && v) atomicOr(&g_or, v);
}

// ---------------- pre-MP linear: g_h = x @ pre_w ---------------------------
__global__ void pre_linear_kernel(const float* __restrict__ x,
                                  const float* __restrict__ w) {
    __shared__ float ws[DIN * DD];
    for (int i = threadIdx.x; i < DIN * DD; i += blockDim.x) ws[i] = w[i];
    __syncthreads();
    int idx = blockIdx.x * blockDim.x + threadIdx.x;
    if (idx >= NN * DD) return;
    int row = idx >> 7;
    int c = idx & 127;
    const float* xr = x + (size_t)row * DIN;
    float acc = 0.f;
#pragma unroll
    for (int kk = 0; kk < DIN; kk++) acc += xr[kk] * ws[kk * DD + c];
    g_h[idx] = acc;
}

// ---------------- BN statistics (per-stage slots) ----------------------------
__global__ void bn_stats_kernel(int which, int stage) {
    const float* xp = which ? g_agg : g_h;
    int c = threadIdx.x;
    float s = 0.f, s2 = 0.f;
#pragma unroll 4
    for (int r = blockIdx.x; r < NN; r += gridDim.x) {
        float v = xp[(size_t)r * DD + c];
        s += v;
        s2 += v * v;
    }
    atomicAdd(&g_sum[stage * DD + c], s);
    atomicAdd(&g_sumsq[stage * DD + c], s2);
}

// ---------------- fused BN finalize -> BN -> ReLU -> l2norm ------------------
__global__ void bn_apply_kernel(int which, int stage,
                                const float* __restrict__ gamma,
                                const float* __restrict__ beta,
                                float* __restrict__ out_ext) {
    __shared__ float smu[DD], srs[DD];
    int t = threadIdx.x;
    if (t < DD) {
        float mu = g_sum[stage * DD + t] * (1.f / NN);
        float var = g_sumsq[stage * DD + t] * (1.f / NN) - mu * mu;
        smu[t] = mu;
        srs[t] = rsqrtf(var + BN_EPS) * gamma[t];
    }
    __syncthreads();
    const float* xp = which ? g_agg : g_h;
    int gt = blockIdx.x * blockDim.x + t;
    int row = gt >> 5;
    int lane = gt & 31;
    if (row >= NN) return;
    int c0 = lane * 4;
    float4 xv = *(const float4*)(xp + (size_t)row * DD + c0);
    float xs[4] = {xv.x, xv.y, xv.z, xv.w};
    float y[4];
    float ss = 0.f;
#pragma unroll
    for (int j = 0; j < 4; j++) {
        int c = c0 + j;
        float val = (xs[j] - smu[c]) * srs[c] + beta[c];
        val = fmaxf(val, 0.f);
        y[j] = val;
        ss += val * val;
    }
#pragma unroll
    for (int o = 16; o > 0; o >>= 1) ss += __shfl_xor_sync(0xffffffffu, ss, o);
    float sc = 1.f / fmaxf(sqrtf(ss), 1e-12f);
    float* op = out_ext ? out_ext : g_h;
    float4 ov = make_float4(y[0] * sc, y[1] * sc, y[2] * sc, y[3] * sc);
    *(float4*)(op + (size_t)row * DD + c0) = ov;
}

// ---------------- 4-way SGEMM with packed f32x2 FMAs -------------------------
// grid (8, ceil(NN/128)); blockIdx.x selects (matrix, 64-col half).
// Block: 128 rows x 64 cols, K=128. 256 threads, microtile 8 rows x 4 cols.
// f32x2 pair dimension runs along K (even/odd partial sums, folded at the end),
// so A and B fragments load as packed u64 directly from shared: no pack MOVs.
// Thread cols are (col0 + tx + 16j) so B LDS across the 16 tx lanes is
// stride-132-words => conflict-free 2-phase LDS.128.
__global__ void gemm4_kernel(const float* __restrict__ wkp,
                             const float* __restrict__ wqp,
                             const float* __restrict__ wvp,
                             const float* __restrict__ wsp) {
    extern __shared__ float sm[];
    float* As = sm;                // [128 rows][128 k]
    float* Bt = sm + 128 * 128;    // [64 cols][BPAD k]
    int t = threadIdx.x;
    int mat = blockIdx.x >> 1;
    int col0 = (blockIdx.x & 1) * 64;
    const float* W = (mat == 0) ? wkp : (mat == 1) ? wqp : (mat == 2) ? wvp : wsp;
    float* O = (mat == 0) ? g_k : (mat == 1) ? g_q : (mat == 2) ? g_v : g_agg;
    int row0 = blockIdx.y * 128;

    // A tile: coalesced float4, zero-fill OOB rows. Conflict-free STS.128.
    {
        int k4 = t & 31;
        int r0 = t >> 5;
#pragma unroll
        for (int rr = r0; rr < 128; rr += 8) {
            float4 val = make_float4(0.f, 0.f, 0.f, 0.f);
            int grow = row0 + rr;
            if (grow < NN) val = *(const float4*)(g_h + (size_t)grow * DD + k4 * 4);
            *(float4*)(As + rr * 128 + k4 * 4) = val;
        }
    }
    // B tile transposed: Bt[col][k] = W[k][col0+col]; coalesced global reads.
    {
        int c = t & 63;
        int k0 = t >> 6;
#pragma unroll
        for (int kk = k0; kk < 128; kk += 4)
            Bt[c * BPAD + kk] = W[kk * DD + col0 + c];
    }
    __syncthreads();

    int ty = t >> 4, tx = t & 15;
    const float* arow = As + (ty * 8) * 128;

    u64 acc[8][4];
#pragma unroll
    for (int i = 0; i < 8; i++)
#pragma unroll
        for (int j = 0; j < 4; j++) acc[i][j] = 0ull;

#pragma unroll 4
    for (int kk = 0; kk < 128; kk += 4) {
        u64 b[4][2];
#pragma unroll
        for (int j = 0; j < 4; j++) {
            const u64* bp = (const u64*)(Bt + (tx + 16 * j) * BPAD + kk);
            b[j][0] = bp[0];
            b[j][1] = bp[1];
        }
#pragma unroll
        for (int i = 0; i < 8; i++) {
            const u64* ap = (const u64*)(arow + i * 128 + kk);
            u64 a0 = ap[0], a1 = ap[1];
#pragma unroll
            for (int j = 0; j < 4; j++) {
                ffma2(acc[i][j], a0, b[j][0]);
                ffma2(acc[i][j], a1, b[j][1]);
            }
        }
    }

    int crow0 = row0 + ty * 8;
#pragma unroll
    for (int i = 0; i < 8; i++) {
        int grow = crow0 + i;
        if (grow < NN) {
            float* orow = O + (size_t)grow * DD + col0 + tx;
#pragma unroll
            for (int j = 0; j < 4; j++) orow[16 * j] = fold2(acc[i][j]);
        }
    }
}

// ---------------- edge message + scatter (one warp per edge) ----------------
__global__ void edge_kernel(const int* __restrict__ ei) {
    long long gt = blockIdx.x * (long long)blockDim.x + threadIdx.x;
    int e = (int)(gt >> 5);
    int lane = (int)(gt & 31);
    if (e >= EE) return;
    int s, d;
    if (g_or == 0u) {  // int64 edge_index
        const long long* e64 = (const long long*)ei;
        s = (int)e64[e];
        d = (int)e64[EE + e];
    } else {           // int32 edge_index
        s = __ldg(ei + e);
        d = __ldg(ei + EE + e);
    }
    size_t so = (size_t)s * DD + lane * 4;
    size_t dofs = (size_t)d * DD + lane * 4;
    float4 kk = __ldg((const float4*)(g_k + dofs));
    float4 qq = __ldg((const float4*)(g_q + so));
    float4 vv = __ldg((const float4*)(g_v + so));
    float4 m;
    m.x = vv.x / (1.f + __expf(-(kk.x + qq.x)));
    m.y = vv.y / (1.f + __expf(-(kk.y + qq.y)));
    m.z = vv.z / (1.f + __expf(-(kk.z + qq.z)));
    m.w = vv.w / (1.f + __expf(-(kk.w + qq.w)));
    asm volatile("red.global.add.v4.f32 [%0], {%1,%2,%3,%4};"
                 :: "l"(g_agg + dofs), "f"(m.x), "f"(m.y), "f"(m.z), "f"(m.w)
                 : "memory");
}

// ---------------- launch ----------------------------------------------------
extern "C" void kernel_launch(void* const* d_in, const int* in_sizes, int n_in,
                              void* d_out, int out_size) {
    const float* x     = (const float*)d_in[0];
    const int*   ei    = (const int*)d_in[1];
    const float* pre_w = (const float*)d_in[2];
    const float* pre_g = (const float*)d_in[3];
    const float* pre_b = (const float*)d_in[4];
    const float* wk    = (const float*)d_in[5];
    const float* wq    = (const float*)d_in[6];
    const float* wv    = (const float*)d_in[7];
    const float* ws    = (const float*)d_in[8];
    const float* mg    = (const float*)d_in[9];
    const float* mb    = (const float*)d_in[10];
    float* outp = (float*)d_out;

    cudaFuncSetAttribute(gemm4_kernel,
                         cudaFuncAttributeMaxDynamicSharedMemorySize,
                         (int)GEMM_SMEM);

    init_kernel<<<1, 128>>>();
    detect_kernel<<<256, 256>>>((const unsigned int*)ei);

    // pre-MP: linear -> BN -> ReLU -> l2norm
    pre_linear_kernel<<<(NN * DD + 255) / 256, 256>>>(x, pre_w);
    bn_stats_kernel<<<256, DD>>>(0, 0);
    bn_apply_kernel<<<(NN + 7) / 8, 256>>>(0, 0, pre_g, pre_b, nullptr);

    const int gemm_gy = (NN + 127) / 128;
    for (int l = 0; l < 2; l++) {
        gemm4_kernel<<<dim3(8, gemm_gy), 256, GEMM_SMEM>>>(
            wk + l * DD * DD, wq + l * DD * DD, wv + l * DD * DD, ws + l * DD * DD);
        edge_kernel<<<(int)(((long long)EE * 32 + 255) / 256), 256>>>(ei);
        bn_stats_kernel<<<256, DD>>>(1, 1 + l);
        bn_apply_kernel<<<(NN + 7) / 8, 256>>>(
            1, 1 + l, mg + l * DD, mb + l * DD, (l == 1) ? outp : nullptr);
    }
}

// round 3
// speedup vs baseline: 1.5594x; 1.2119x over previous
#include <cuda_runtime.h>
#include <math.h>

#define NN 50000
#define EE 800000
#define DIN 20
#define DD 128
#define BN_EPS 1e-5f

#define BPAD 132
#define GEMM_SMEM (size_t)((128 * 128 + 64 * BPAD) * sizeof(float))

typedef unsigned long long u64;

// ---------------- scratch (device globals; no runtime allocation) ----------
__device__ float g_h[NN * DD];
__device__ float g_k[NN * DD];
__device__ float g_q[NN * DD];
__device__ float g_v[NN * DD];
__device__ float g_agg[NN * DD];
__device__ float g_sum[3 * DD], g_sumsq[3 * DD];
__device__ int g_src[EE], g_dst[EE];
__device__ unsigned int g_or;  // OR of odd int32 words of edge row 0 (0 => int64)

// ---------------- f32x2 helpers ---------------------------------------------
__device__ __forceinline__ void ffma2(u64& d, u64 a, u64 b) {
    asm("fma.rn.f32x2 %0, %1, %2, %3;" : "=l"(d) : "l"(a), "l"(b), "l"(d));
}
__device__ __forceinline__ float fold2(u64 v) {
    float lo, hi;
    asm("mov.b64 {%0,%1}, %2;" : "=f"(lo), "=f"(hi) : "l"(v));
    return lo + hi;
}

// ---------------- init: zero detection flag + all BN stat slots -------------
__global__ void init_kernel() {
    int t = threadIdx.x;
    if (t == 0) g_or = 0u;
    for (int i = t; i < 3 * DD; i += blockDim.x) {
        g_sum[i] = 0.f;
        g_sumsq[i] = 0.f;
    }
}

__global__ void detect_kernel(const unsigned int* __restrict__ w) {
    unsigned int v = 0;
    for (long long i = blockIdx.x * (long long)blockDim.x + threadIdx.x;
         i < EE; i += (long long)gridDim.x * blockDim.x)
        v |= w[2 * i + 1];
#pragma unroll
    for (int o = 16; o > 0; o >>= 1) v |= __shfl_xor_sync(0xffffffffu, v, o);
    if ((threadIdx.x & 31) == 0 && v) atomicOr(&g_or, v);
}

// Convert edge_index (either dtype) into int32 src/dst arrays once per call.
__global__ void convert_kernel(const int* __restrict__ ei) {
    int i = blockIdx.x * blockDim.x + threadIdx.x;
    if (i >= EE) return;
    if (g_or == 0u) {  // int64
        const long long* e64 = (const long long*)ei;
        g_src[i] = (int)e64[i];
        g_dst[i] = (int)e64[EE + i];
    } else {           // int32
        g_src[i] = ei[i];
        g_dst[i] = ei[EE + i];
    }
}

// ---------------- pre-MP linear: g_h = x @ pre_w ---------------------------
__global__ void pre_linear_kernel(const float* __restrict__ x,
                                  const float* __restrict__ w) {
    __shared__ float ws[DIN * DD];
    for (int i = threadIdx.x; i < DIN * DD; i += blockDim.x) ws[i] = w[i];
    __syncthreads();
    int idx = blockIdx.x * blockDim.x + threadIdx.x;
    if (idx >= NN * DD) return;
    int row = idx >> 7;
    int c = idx & 127;
    const float* xr = x + (size_t)row * DIN;
    float acc = 0.f;
#pragma unroll
    for (int kk = 0; kk < DIN; kk++) acc += xr[kk] * ws[kk * DD + c];
    g_h[idx] = acc;
}

// ---------------- BN statistics: wide-parallel, float4, block reduction -----
__global__ void bn_stats_kernel(int which, int stage) {
    const float* xp = which ? g_agg : g_h;
    __shared__ float ssum[DD], ssq[DD];
    int t = threadIdx.x;  // 256
    if (t < DD) {
        ssum[t] = 0.f;
        ssq[t] = 0.f;
    }
    __syncthreads();
    int c0 = (t & 31) * 4;
    int rw = t >> 5;  // 0..7 row lane within block
    float s0 = 0.f, s1 = 0.f, s2 = 0.f, s3 = 0.f;
    float q0 = 0.f, q1 = 0.f, q2 = 0.f, q3 = 0.f;
#pragma unroll 4
    for (int r = blockIdx.x * 8 + rw; r < NN; r += gridDim.x * 8) {
        float4 v = *(const float4*)(xp + (size_t)r * DD + c0);
        s0 += v.x; s1 += v.y; s2 += v.z; s3 += v.w;
        q0 += v.x * v.x; q1 += v.y * v.y; q2 += v.z * v.z; q3 += v.w * v.w;
    }
    atomicAdd(&ssum[c0 + 0], s0);
    atomicAdd(&ssum[c0 + 1], s1);
    atomicAdd(&ssum[c0 + 2], s2);
    atomicAdd(&ssum[c0 + 3], s3);
    atomicAdd(&ssq[c0 + 0], q0);
    atomicAdd(&ssq[c0 + 1], q1);
    atomicAdd(&ssq[c0 + 2], q2);
    atomicAdd(&ssq[c0 + 3], q3);
    __syncthreads();
    if (t < DD) {
        atomicAdd(&g_sum[stage * DD + t], ssum[t]);
        atomicAdd(&g_sumsq[stage * DD + t], ssq[t]);
    }
}

// ---------------- fused BN finalize -> BN -> ReLU -> l2norm ------------------
__global__ void bn_apply_kernel(int which, int stage,
                                const float* __restrict__ gamma,
                                const float* __restrict__ beta,
                                float* __restrict__ out_ext) {
    __shared__ float smu[DD], srs[DD];
    int t = threadIdx.x;
    if (t < DD) {
        float mu = g_sum[stage * DD + t] * (1.f / NN);
        float var = g_sumsq[stage * DD + t] * (1.f / NN) - mu * mu;
        smu[t] = mu;
        srs[t] = rsqrtf(var + BN_EPS) * gamma[t];
    }
    __syncthreads();
    const float* xp = which ? g_agg : g_h;
    int gt = blockIdx.x * blockDim.x + t;
    int row = gt >> 5;
    int lane = gt & 31;
    if (row >= NN) return;
    int c0 = lane * 4;
    float4 xv = *(const float4*)(xp + (size_t)row * DD + c0);
    float xs[4] = {xv.x, xv.y, xv.z, xv.w};
    float y[4];
    float ss = 0.f;
#pragma unroll
    for (int j = 0; j < 4; j++) {
        int c = c0 + j;
        float val = (xs[j] - smu[c]) * srs[c] + beta[c];
        val = fmaxf(val, 0.f);
        y[j] = val;
        ss += val * val;
    }
#pragma unroll
    for (int o = 16; o > 0; o >>= 1) ss += __shfl_xor_sync(0xffffffffu, ss, o);
    float sc = 1.f / fmaxf(sqrtf(ss), 1e-12f);
    float* op = out_ext ? out_ext : g_h;
    float4 ov = make_float4(y[0] * sc, y[1] * sc, y[2] * sc, y[3] * sc);
    *(float4*)(op + (size_t)row * DD + c0) = ov;
}

// ---------------- 4-way SGEMM with packed f32x2 FMAs -------------------------
__global__ void gemm4_kernel(const float* __restrict__ wkp,
                             const float* __restrict__ wqp,
                             const float* __restrict__ wvp,
                             const float* __restrict__ wsp) {
    extern __shared__ float sm[];
    float* As = sm;                // [128 rows][128 k]
    float* Bt = sm + 128 * 128;    // [64 cols][BPAD k]
    int t = threadIdx.x;
    int mat = blockIdx.x >> 1;
    int col0 = (blockIdx.x & 1) * 64;
    const float* W = (mat == 0) ? wkp : (mat == 1) ? wqp : (mat == 2) ? wvp : wsp;
    float* O = (mat == 0) ? g_k : (mat == 1) ? g_q : (mat == 2) ? g_v : g_agg;
    int row0 = blockIdx.y * 128;

    {
        int k4 = t & 31;
        int r0 = t >> 5;
#pragma unroll
        for (int rr = r0; rr < 128; rr += 8) {
            float4 val = make_float4(0.f, 0.f, 0.f, 0.f);
            int grow = row0 + rr;
            if (grow < NN) val = *(const float4*)(g_h + (size_t)grow * DD + k4 * 4);
            *(float4*)(As + rr * 128 + k4 * 4) = val;
        }
    }
    {
        int c = t & 63;
        int k0 = t >> 6;
#pragma unroll
        for (int kk = k0; kk < 128; kk += 4)
            Bt[c * BPAD + kk] = W[kk * DD + col0 + c];
    }
    __syncthreads();

    int ty = t >> 4, tx = t & 15;
    const float* arow = As + (ty * 8) * 128;

    u64 acc[8][4];
#pragma unroll
    for (int i = 0; i < 8; i++)
#pragma unroll
        for (int j = 0; j < 4; j++) acc[i][j] = 0ull;

#pragma unroll 4
    for (int kk = 0; kk < 128; kk += 4) {
        u64 b[4][2];
#pragma unroll
        for (int j = 0; j < 4; j++) {
            const u64* bp = (const u64*)(Bt + (tx + 16 * j) * BPAD + kk);
            b[j][0] = bp[0];
            b[j][1] = bp[1];
        }
#pragma unroll
        for (int i = 0; i < 8; i++) {
            const u64* ap = (const u64*)(arow + i * 128 + kk);
            u64 a0 = ap[0], a1 = ap[1];
#pragma unroll
            for (int j = 0; j < 4; j++) {
                ffma2(acc[i][j], a0, b[j][0]);
                ffma2(acc[i][j], a1, b[j][1]);
            }
        }
    }

    int crow0 = row0 + ty * 8;
#pragma unroll
    for (int i = 0; i < 8; i++) {
        int grow = crow0 + i;
        if (grow < NN) {
            float* orow = O + (size_t)grow * DD + col0 + tx;
#pragma unroll
            for (int j = 0; j < 4; j++) orow[16 * j] = fold2(acc[i][j]);
        }
    }
}

// ---------------- edge message + scatter (one warp per edge) ----------------
__global__ void edge_kernel() {
    long long gt = blockIdx.x * (long long)blockDim.x + threadIdx.x;
    int e = (int)(gt >> 5);
    int lane = (int)(gt & 31);
    if (e >= EE) return;
    int s = __ldg(g_src + e);
    int d = __ldg(g_dst + e);
    size_t so = (size_t)s * DD + lane * 4;
    size_t dofs = (size_t)d * DD + lane * 4;
    float4 kk = __ldg((const float4*)(g_k + dofs));
    float4 qq = __ldg((const float4*)(g_q + so));
    float4 vv = __ldg((const float4*)(g_v + so));
    float4 m;
    m.x = vv.x / (1.f + __expf(-(kk.x + qq.x)));
    m.y = vv.y / (1.f + __expf(-(kk.y + qq.y)));
    m.z = vv.z / (1.f + __expf(-(kk.z + qq.z)));
    m.w = vv.w / (1.f + __expf(-(kk.w + qq.w)));
    asm volatile("red.global.add.v4.f32 [%0], {%1,%2,%3,%4};"
                 :: "l"(g_agg + dofs), "f"(m.x), "f"(m.y), "f"(m.z), "f"(m.w)
                 : "memory");
}

// ---------------- launch ----------------------------------------------------
extern "C" void kernel_launch(void* const* d_in, const int* in_sizes, int n_in,
                              void* d_out, int out_size) {
    const float* x     = (const float*)d_in[0];
    const int*   ei    = (const int*)d_in[1];
    const float* pre_w = (const float*)d_in[2];
    const float* pre_g = (const float*)d_in[3];
    const float* pre_b = (const float*)d_in[4];
    const float* wk    = (const float*)d_in[5];
    const float* wq    = (const float*)d_in[6];
    const float* wv    = (const float*)d_in[7];
    const float* ws    = (const float*)d_in[8];
    const float* mg    = (const float*)d_in[9];
    const float* mb    = (const float*)d_in[10];
    float* outp = (float*)d_out;

    cudaFuncSetAttribute(gemm4_kernel,
                         cudaFuncAttributeMaxDynamicSharedMemorySize,
                         (int)GEMM_SMEM);

    init_kernel<<<1, 128>>>();
    detect_kernel<<<256, 256>>>((const unsigned int*)ei);
    convert_kernel<<<(EE + 255) / 256, 256>>>(ei);

    // pre-MP: linear -> BN -> ReLU -> l2norm
    pre_linear_kernel<<<(NN * DD + 255) / 256, 256>>>(x, pre_w);
    bn_stats_kernel<<<512, 256>>>(0, 0);
    bn_apply_kernel<<<(NN + 7) / 8, 256>>>(0, 0, pre_g, pre_b, nullptr);

    const int gemm_gy = (NN + 127) / 128;
    for (int l = 0; l < 2; l++) {
        gemm4_kernel<<<dim3(8, gemm_gy), 256, GEMM_SMEM>>>(
            wk + l * DD * DD, wq + l * DD * DD, wv + l * DD * DD, ws + l * DD * DD);
        edge_kernel<<<(int)(((long long)EE * 32 + 255) / 256), 256>>>();
        bn_stats_kernel<<<512, 256>>>(1, 1 + l);
        bn_apply_kernel<<<(NN + 7) / 8, 256>>>(
            1, 1 + l, mg + l * DD, mb + l * DD, (l == 1) ? outp : nullptr);
    }
}

// round 4
// speedup vs baseline: 1.6831x; 1.0794x over previous
#include <cuda_runtime.h>
#include <cuda_fp16.h>
#include <math.h>

#define NN 50000
#define EE 800000
#define DIN 20
#define DD 128
#define BN_EPS 1e-5f

#define BPAD 132
#define GEMM_SMEM (size_t)((128 * 128 + 64 * BPAD) * sizeof(float))

typedef unsigned long long u64;

// ---------------- scratch (device globals; no runtime allocation) ----------
__device__ float g_h[NN * DD];
__device__ __half g_kh[NN * DD];   // k in fp16 (gate input only)
__device__ __half g_qh[NN * DD];   // q in fp16 (gate input only)
__device__ float g_v[NN * DD];
__device__ float g_agg[NN * DD];
__device__ float g_sum[3 * DD], g_sumsq[3 * DD];
__device__ int g_src[EE], g_dst[EE];
__device__ unsigned int g_or;  // OR of odd int32 words of edge row 0 (0 => int64)

// ---------------- f32x2 helpers ---------------------------------------------
__device__ __forceinline__ void ffma2(u64& d, u64 a, u64 b) {
    asm("fma.rn.f32x2 %0, %1, %2, %3;" : "=l"(d) : "l"(a), "l"(b), "l"(d));
}
__device__ __forceinline__ float fold2(u64 v) {
    float lo, hi;
    asm("mov.b64 {%0,%1}, %2;" : "=f"(lo), "=f"(hi) : "l"(v));
    return lo + hi;
}

// ---------------- init ------------------------------------------------------
__global__ void init_kernel() {
    int t = threadIdx.x;
    if (t == 0) g_or = 0u;
    for (int i = t; i < 3 * DD; i += blockDim.x) {
        g_sum[i] = 0.f;
        g_sumsq[i] = 0.f;
    }
}

__global__ void detect_kernel(const unsigned int* __restrict__ w) {
    unsigned int v = 0;
    for (long long i = blockIdx.x * (long long)blockDim.x + threadIdx.x;
         i < EE; i += (long long)gridDim.x * blockDim.x)
        v |= w[2 * i + 1];
#pragma unroll
    for (int o = 16; o > 0; o >>= 1) v |= __shfl_xor_sync(0xffffffffu, v, o);
    if ((threadIdx.x & 31) == 0 && v) atomicOr(&g_or, v);
}

__global__ void convert_kernel(const int* __restrict__ ei) {
    int i = blockIdx.x * blockDim.x + threadIdx.x;
    if (i >= EE) return;
    if (g_or == 0u) {  // int64
        const long long* e64 = (const long long*)ei;
        g_src[i] = (int)e64[i];
        g_dst[i] = (int)e64[EE + i];
    } else {           // int32
        g_src[i] = ei[i];
        g_dst[i] = ei[EE + i];
    }
}

// ---------------- pre-MP linear + fused stage-0 BN stats --------------------
// 256 threads = 2 rows x 128 cols; 32 rows per block. x staged via smem.
#define PL_ROWS 32
__global__ void pre_linear_kernel(const float* __restrict__ x,
                                  const float* __restrict__ w) {
    __shared__ float ws[DIN * DD];
    __shared__ float xs[2][DIN];
    __shared__ float ssum[DD], ssq[DD];
    int t = threadIdx.x;
    int c = t & 127;
    int rl = t >> 7;  // 0..1
    for (int i = t; i < DIN * DD; i += 256) ws[i] = w[i];
    if (t < DD) {
        ssum[t] = 0.f;
        ssq[t] = 0.f;
    }
    int row0 = blockIdx.x * PL_ROWS;
    float s = 0.f, s2 = 0.f;
    for (int r2 = 0; r2 < PL_ROWS; r2 += 2) {
        __syncthreads();
        if (t < 2 * DIN) {
            int rr = t / DIN, kk = t % DIN;
            int grow = row0 + r2 + rr;
            xs[rr][kk] = (grow < NN) ? x[(size_t)grow * DIN + kk] : 0.f;
        }
        __syncthreads();
        int grow = row0 + r2 + rl;
        float acc = 0.f;
#pragma unroll
        for (int kk = 0; kk < DIN; kk++) acc += xs[rl][kk] * ws[kk * DD + c];
        if (grow < NN) {
            g_h[(size_t)grow * DD + c] = acc;
            s += acc;
            s2 += acc * acc;
        }
    }
    atomicAdd(&ssum[c], s);
    atomicAdd(&ssq[c], s2);
    __syncthreads();
    if (t < DD) {
        atomicAdd(&g_sum[t], ssum[t]);
        atomicAdd(&g_sumsq[t], ssq[t]);
    }
}

// ---------------- BN statistics (agg stages) ---------------------------------
__global__ void bn_stats_kernel(int stage) {
    const float* xp = g_agg;
    __shared__ float ssum[DD], ssq[DD];
    int t = threadIdx.x;  // 256
    if (t < DD) {
        ssum[t] = 0.f;
        ssq[t] = 0.f;
    }
    __syncthreads();
    int c0 = (t & 31) * 4;
    int rw = t >> 5;
    float s0 = 0.f, s1 = 0.f, s2 = 0.f, s3 = 0.f;
    float q0 = 0.f, q1 = 0.f, q2 = 0.f, q3 = 0.f;
#pragma unroll 4
    for (int r = blockIdx.x * 8 + rw; r < NN; r += gridDim.x * 8) {
        float4 v = *(const float4*)(xp + (size_t)r * DD + c0);
        s0 += v.x; s1 += v.y; s2 += v.z; s3 += v.w;
        q0 += v.x * v.x; q1 += v.y * v.y; q2 += v.z * v.z; q3 += v.w * v.w;
    }
    atomicAdd(&ssum[c0 + 0], s0);
    atomicAdd(&ssum[c0 + 1], s1);
    atomicAdd(&ssum[c0 + 2], s2);
    atomicAdd(&ssum[c0 + 3], s3);
    atomicAdd(&ssq[c0 + 0], q0);
    atomicAdd(&ssq[c0 + 1], q1);
    atomicAdd(&ssq[c0 + 2], q2);
    atomicAdd(&ssq[c0 + 3], q3);
    __syncthreads();
    if (t < DD) {
        atomicAdd(&g_sum[stage * DD + t], ssum[t]);
        atomicAdd(&g_sumsq[stage * DD + t], ssq[t]);
    }
}

// ---------------- fused BN finalize -> BN -> ReLU -> l2norm ------------------
__global__ void bn_apply_kernel(int which, int stage,
                                const float* __restrict__ gamma,
                                const float* __restrict__ beta,
                                float* __restrict__ out_ext) {
    __shared__ float smu[DD], srs[DD];
    int t = threadIdx.x;
    if (t < DD) {
        float mu = g_sum[stage * DD + t] * (1.f / NN);
        float var = g_sumsq[stage * DD + t] * (1.f / NN) - mu * mu;
        smu[t] = mu;
        srs[t] = rsqrtf(var + BN_EPS) * gamma[t];
    }
    __syncthreads();
    const float* xp = which ? g_agg : g_h;
    int gt = blockIdx.x * blockDim.x + t;
    int row = gt >> 5;
    int lane = gt & 31;
    if (row >= NN) return;
    int c0 = lane * 4;
    float4 xv = *(const float4*)(xp + (size_t)row * DD + c0);
    float xs[4] = {xv.x, xv.y, xv.z, xv.w};
    float y[4];
    float ss = 0.f;
#pragma unroll
    for (int j = 0; j < 4; j++) {
        int c = c0 + j;
        float val = (xs[j] - smu[c]) * srs[c] + beta[c];
        val = fmaxf(val, 0.f);
        y[j] = val;
        ss += val * val;
    }
#pragma unroll
    for (int o = 16; o > 0; o >>= 1) ss += __shfl_xor_sync(0xffffffffu, ss, o);
    float sc = 1.f / fmaxf(sqrtf(ss), 1e-12f);
    float* op = out_ext ? out_ext : g_h;
    float4 ov = make_float4(y[0] * sc, y[1] * sc, y[2] * sc, y[3] * sc);
    *(float4*)(op + (size_t)row * DD + c0) = ov;
}

// ---------------- 4-way SGEMM with packed f32x2 FMAs -------------------------
// k,q results stored as fp16 (gate precision is ample); v,skip stay fp32.
__global__ void gemm4_kernel(const float* __restrict__ wkp,
                             const float* __restrict__ wqp,
                             const float* __restrict__ wvp,
                             const float* __restrict__ wsp) {
    extern __shared__ float sm[];
    float* As = sm;                // [128 rows][128 k]
    float* Bt = sm + 128 * 128;    // [64 cols][BPAD k]
    int t = threadIdx.x;
    int mat = blockIdx.x >> 1;
    int col0 = (blockIdx.x & 1) * 64;
    const float* W = (mat == 0) ? wkp : (mat == 1) ? wqp : (mat == 2) ? wvp : wsp;
    int row0 = blockIdx.y * 128;

    {
        int k4 = t & 31;
        int r0 = t >> 5;
#pragma unroll
        for (int rr = r0; rr < 128; rr += 8) {
            float4 val = make_float4(0.f, 0.f, 0.f, 0.f);
            int grow = row0 + rr;
            if (grow < NN) val = *(const float4*)(g_h + (size_t)grow * DD + k4 * 4);
            *(float4*)(As + rr * 128 + k4 * 4) = val;
        }
    }
    {
        int c = t & 63;
        int k0 = t >> 6;
#pragma unroll
        for (int kk = k0; kk < 128; kk += 4)
            Bt[c * BPAD + kk] = W[kk * DD + col0 + c];
    }
    __syncthreads();

    int ty = t >> 4, tx = t & 15;
    const float* arow = As + (ty * 8) * 128;

    u64 acc[8][4];
#pragma unroll
    for (int i = 0; i < 8; i++)
#pragma unroll
        for (int j = 0; j < 4; j++) acc[i][j] = 0ull;

#pragma unroll 4
    for (int kk = 0; kk < 128; kk += 4) {
        u64 b[4][2];
#pragma unroll
        for (int j = 0; j < 4; j++) {
            const u64* bp = (const u64*)(Bt + (tx + 16 * j) * BPAD + kk);
            b[j][0] = bp[0];
            b[j][1] = bp[1];
        }
#pragma unroll
        for (int i = 0; i < 8; i++) {
            const u64* ap = (const u64*)(arow + i * 128 + kk);
            u64 a0 = ap[0], a1 = ap[1];
#pragma unroll
            for (int j = 0; j < 4; j++) {
                ffma2(acc[i][j], a0, b[j][0]);
                ffma2(acc[i][j], a1, b[j][1]);
            }
        }
    }

    int crow0 = row0 + ty * 8;
    if (mat < 2) {
        __half* Oh = (mat == 0) ? g_kh : g_qh;
#pragma unroll
        for (int i = 0; i < 8; i++) {
            int grow = crow0 + i;
            if (grow < NN) {
                __half* orow = Oh + (size_t)grow * DD + col0 + tx;
#pragma unroll
                for (int j = 0; j < 4; j++)
                    orow[16 * j] = __float2half_rn(fold2(acc[i][j]));
            }
        }
    } else {
        float* O = (mat == 2) ? g_v : g_agg;
#pragma unroll
        for (int i = 0; i < 8; i++) {
            int grow = crow0 + i;
            if (grow < NN) {
                float* orow = O + (size_t)grow * DD + col0 + tx;
#pragma unroll
                for (int j = 0; j < 4; j++) orow[16 * j] = fold2(acc[i][j]);
            }
        }
    }
}

// ---------------- edge message + scatter (one warp per edge) ----------------
__global__ void edge_kernel() {
    long long gt = blockIdx.x * (long long)blockDim.x + threadIdx.x;
    int e = (int)(gt >> 5);
    int lane = (int)(gt & 31);
    if (e >= EE) return;
    int s = __ldg(g_src + e);
    int d = __ldg(g_dst + e);
    size_t so = (size_t)s * DD + lane * 4;
    size_t dofs = (size_t)d * DD + lane * 4;
    // gate inputs (fp16): 4 halves each = one 8B load
    __half2 k01, k23, q01, q23;
    {
        uint2 kraw = __ldg((const uint2*)(g_kh + dofs));
        uint2 qraw = __ldg((const uint2*)(g_qh + so));
        k01 = *(__half2*)&kraw.x; k23 = *(__half2*)&kraw.y;
        q01 = *(__half2*)&qraw.x; q23 = *(__half2*)&qraw.y;
    }
    float4 vv = __ldg((const float4*)(g_v + so));
    float2 kf0 = __half22float2(k01), kf1 = __half22float2(k23);
    float2 qf0 = __half22float2(q01), qf1 = __half22float2(q23);
    float4 m;
    m.x = vv.x / (1.f + __expf(-(kf0.x + qf0.x)));
    m.y = vv.y / (1.f + __expf(-(kf0.y + qf0.y)));
    m.z = vv.z / (1.f + __expf(-(kf1.x + qf1.x)));
    m.w = vv.w / (1.f + __expf(-(kf1.y + qf1.y)));
    asm volatile("red.global.add.v4.f32 [%0], {%1,%2,%3,%4};"
                 :: "l"(g_agg + dofs), "f"(m.x), "f"(m.y), "f"(m.z), "f"(m.w)
                 : "memory");
}

// ---------------- launch ----------------------------------------------------
extern "C" void kernel_launch(void* const* d_in, const int* in_sizes, int n_in,
                              void* d_out, int out_size) {
    const float* x     = (const float*)d_in[0];
    const int*   ei    = (const int*)d_in[1];
    const float* pre_w = (const float*)d_in[2];
    const float* pre_g = (const float*)d_in[3];
    const float* pre_b = (const float*)d_in[4];
    const float* wk    = (const float*)d_in[5];
    const float* wq    = (const float*)d_in[6];
    const float* wv    = (const float*)d_in[7];
    const float* ws    = (const float*)d_in[8];
    const float* mg    = (const float*)d_in[9];
    const float* mb    = (const float*)d_in[10];
    float* outp = (float*)d_out;

    cudaFuncSetAttribute(gemm4_kernel,
                         cudaFuncAttributeMaxDynamicSharedMemorySize,
                         (int)GEMM_SMEM);

    init_kernel<<<1, 128>>>();
    detect_kernel<<<256, 256>>>((const unsigned int*)ei);
    convert_kernel<<<(EE + 255) / 256, 256>>>(ei);

    // pre-MP: linear (+ fused BN stats) -> BN -> ReLU -> l2norm
    pre_linear_kernel<<<(NN + PL_ROWS - 1) / PL_ROWS, 256>>>(x, pre_w);
    bn_apply_kernel<<<(NN + 7) / 8, 256>>>(0, 0, pre_g, pre_b, nullptr);

    const int gemm_gy = (NN + 127) / 128;
    for (int l = 0; l < 2; l++) {
        gemm4_kernel<<<dim3(8, gemm_gy), 256, GEMM_SMEM>>>(
            wk + l * DD * DD, wq + l * DD * DD, wv + l * DD * DD, ws + l * DD * DD);
        edge_kernel<<<(int)(((long long)EE * 32 + 255) / 256), 256>>>();
        bn_stats_kernel<<<512, 256>>>(1 + l);
        bn_apply_kernel<<<(NN + 7) / 8, 256>>>(
            1, 1 + l, mg + l * DD, mb + l * DD, (l == 1) ? outp : nullptr);
    }
}

// round 5
// speedup vs baseline: 1.7959x; 1.0670x over previous
#include <cuda_runtime.h>
#include <cuda_fp16.h>
#include <math.h>

#define NN 50000
#define EE 800000
#define DIN 20
#define DD 128
#define BN_EPS 1e-5f

#define BPAD 132
#define GEMM_SMEM (size_t)((128 * 128 + 64 * BPAD) * sizeof(float))

#define SB 64          // scan blocks
#define CHUNK 800      // nodes per scan block (64*800 >= 50001)
#define PT 4           // nodes per scan thread (256*4 >= 800)

typedef unsigned long long u64;

// ---------------- scratch (device globals; no runtime allocation) ----------
__device__ float g_h[NN * DD];
__device__ __half g_kh[NN * DD];   // k fp16 (gate input only)
__device__ __half g_qh[NN * DD];   // q fp16 (gate input only)
__device__ float g_v[NN * DD];
__device__ float g_agg[NN * DD];   // skip from GEMM, then skip+sum after agg
__device__ float g_sum[3 * DD], g_sumsq[3 * DD];
__device__ int g_src[EE], g_dst[EE];
__device__ int g_deg[NN + 1];      // histogram of dst
__device__ int g_off[NN + 1];      // CSR offsets
__device__ int g_pos[NN];          // scatter fill cursors
__device__ int g_esrc[EE];         // src ids grouped by dst
__device__ int g_bsum[SB], g_bpre[SB];
__device__ unsigned int g_or;      // 0 => edge_index is int64

// ---------------- f32x2 helpers ---------------------------------------------
__device__ __forceinline__ void ffma2(u64& d, u64 a, u64 b) {
    asm("fma.rn.f32x2 %0, %1, %2, %3;" : "=l"(d) : "l"(a), "l"(b), "l"(d));
}
__device__ __forceinline__ float fold2(u64 v) {
    float lo, hi;
    asm("mov.b64 {%0,%1}, %2;" : "=f"(lo), "=f"(hi) : "l"(v));
    return lo + hi;
}

// ---------------- init: zero flag, stats, histogram --------------------------
__global__ void init_kernel() {
    int i = blockIdx.x * blockDim.x + threadIdx.x;
    if (i == 0) g_or = 0u;
    if (i < 3 * DD) {
        g_sum[i] = 0.f;
        g_sumsq[i] = 0.f;
    }
    if (i <= NN) g_deg[i] = 0;
}

__global__ void detect_kernel(const unsigned int* __restrict__ w) {
    unsigned int v = 0;
    for (long long i = blockIdx.x * (long long)blockDim.x + threadIdx.x;
         i < EE; i += (long long)gridDim.x * blockDim.x)
        v |= w[2 * i + 1];
#pragma unroll
    for (int o = 16; o > 0; o >>= 1) v |= __shfl_xor_sync(0xffffffffu, v, o);
    if ((threadIdx.x & 31) == 0 && v) atomicOr(&g_or, v);
}

// convert to int32 + dst histogram
__global__ void convert_kernel(const int* __restrict__ ei) {
    int i = blockIdx.x * blockDim.x + threadIdx.x;
    if (i >= EE) return;
    int s, d;
    if (g_or == 0u) {
        const long long* e64 = (const long long*)ei;
        s = (int)e64[i];
        d = (int)e64[EE + i];
    } else {
        s = ei[i];
        d = ei[EE + i];
    }
    g_src[i] = s;
    g_dst[i] = d;
    atomicAdd(&g_deg[d], 1);
}

// ---------------- 3-kernel exclusive scan of g_deg -> g_off ------------------
__global__ void scan1_kernel() {
    __shared__ int sh[256];
    int b = blockIdx.x, t = threadIdx.x;
    int base = b * CHUNK + t * PT;
    int s = 0;
#pragma unroll
    for (int j = 0; j < PT; j++) {
        int idx = base + j;
        if (idx < b * CHUNK + CHUNK && idx < NN) s += g_deg[idx];
    }
    sh[t] = s;
    __syncthreads();
    for (int o = 128; o > 0; o >>= 1) {
        if (t < o) sh[t] += sh[t + o];
        __syncthreads();
    }
    if (t == 0) g_bsum[b] = sh[0];
}

__global__ void scan2_kernel() {
    __shared__ int sh[SB];
    int t = threadIdx.x;
    sh[t] = g_bsum[t];
    __syncthreads();
    if (t == 0) {
        int run = 0;
        for (int i = 0; i < SB; i++) {
            int v = sh[i];
            sh[i] = run;
            run += v;
        }
    }
    __syncthreads();
    g_bpre[t] = sh[t];
}

__global__ void scan3_kernel() {
    __shared__ int arr[256];
    int b = blockIdx.x, t = threadIdx.x;
    int base = b * CHUNK + t * PT;
    int dv[PT];
    int tsum = 0;
#pragma unroll
    for (int j = 0; j < PT; j++) {
        int idx = base + j;
        dv[j] = (idx < b * CHUNK + CHUNK && idx < NN) ? g_deg[idx] : 0;
        tsum += dv[j];
    }
    arr[t] = tsum;
    __syncthreads();
#pragma unroll
    for (int o = 1; o < 256; o <<= 1) {
        int v = (t >= o) ? arr[t - o] : 0;
        __syncthreads();
        arr[t] += v;
        __syncthreads();
    }
    int run = g_bpre[b] + arr[t] - tsum;
#pragma unroll
    for (int j = 0; j < PT; j++) {
        int idx = base + j;
        if (idx < b * CHUNK + CHUNK && idx < NN) {
            g_off[idx] = run;
            g_pos[idx] = run;
            run += dv[j];
        }
    }
    if (b == 0 && t == 0) g_off[NN] = EE;
}

__global__ void scatter_kernel() {
    int i = blockIdx.x * blockDim.x + threadIdx.x;
    if (i >= EE) return;
    int d = g_dst[i];
    int p = atomicAdd(&g_pos[d], 1);
    g_esrc[p] = g_src[i];
}

// ---------------- pre-MP linear + fused stage-0 BN stats --------------------
// 256 threads = 2 rows x 128 cols; 32 rows/block; x staged once; weights in regs.
#define PL_ROWS 32
__global__ void pre_linear_kernel(const float* __restrict__ x,
                                  const float* __restrict__ w) {
    __shared__ float xs[PL_ROWS][DIN];
    __shared__ float ssum[DD], ssq[DD];
    int t = threadIdx.x;
    int c = t & 127;
    int rl = t >> 7;  // 0..1
    float wr[DIN];
#pragma unroll
    for (int kk = 0; kk < DIN; kk++) wr[kk] = w[kk * DD + c];
    if (t < DD) {
        ssum[t] = 0.f;
        ssq[t] = 0.f;
    }
    int row0 = blockIdx.x * PL_ROWS;
    for (int i = t; i < PL_ROWS * DIN; i += 256) {
        int rr = i / DIN, kk = i % DIN;
        int grow = row0 + rr;
        xs[rr][kk] = (grow < NN) ? x[(size_t)grow * DIN + kk] : 0.f;
    }
    __syncthreads();
    float s = 0.f, s2 = 0.f;
#pragma unroll 4
    for (int r2 = 0; r2 < PL_ROWS; r2 += 2) {
        int r = r2 + rl;
        int grow = row0 + r;
        float acc = 0.f;
#pragma unroll
        for (int kk = 0; kk < DIN; kk++) acc += xs[r][kk] * wr[kk];
        if (grow < NN) {
            g_h[(size_t)grow * DD + c] = acc;
            s += acc;
            s2 += acc * acc;
        }
    }
    atomicAdd(&ssum[c], s);
    atomicAdd(&ssq[c], s2);
    __syncthreads();
    if (t < DD) {
        atomicAdd(&g_sum[t], ssum[t]);
        atomicAdd(&g_sumsq[t], ssq[t]);
    }
}

// ---------------- fused BN finalize -> BN -> ReLU -> l2norm ------------------
__global__ void bn_apply_kernel(int which, int stage,
                                const float* __restrict__ gamma,
                                const float* __restrict__ beta,
                                float* __restrict__ out_ext) {
    __shared__ float smu[DD], srs[DD];
    int t = threadIdx.x;
    if (t < DD) {
        float mu = g_sum[stage * DD + t] * (1.f / NN);
        float var = g_sumsq[stage * DD + t] * (1.f / NN) - mu * mu;
        smu[t] = mu;
        srs[t] = rsqrtf(var + BN_EPS) * gamma[t];
    }
    __syncthreads();
    const float* xp = which ? g_agg : g_h;
    int gt = blockIdx.x * blockDim.x + t;
    int row = gt >> 5;
    int lane = gt & 31;
    if (row >= NN) return;
    int c0 = lane * 4;
    float4 xv = *(const float4*)(xp + (size_t)row * DD + c0);
    float xsv[4] = {xv.x, xv.y, xv.z, xv.w};
    float y[4];
    float ss = 0.f;
#pragma unroll
    for (int j = 0; j < 4; j++) {
        int c = c0 + j;
        float val = (xsv[j] - smu[c]) * srs[c] + beta[c];
        val = fmaxf(val, 0.f);
        y[j] = val;
        ss += val * val;
    }
#pragma unroll
    for (int o = 16; o > 0; o >>= 1) ss += __shfl_xor_sync(0xffffffffu, ss, o);
    float sc = 1.f / fmaxf(sqrtf(ss), 1e-12f);
    float* op = out_ext ? out_ext : g_h;
    float4 ov = make_float4(y[0] * sc, y[1] * sc, y[2] * sc, y[3] * sc);
    *(float4*)(op + (size_t)row * DD + c0) = ov;
}

// ---------------- 4-way SGEMM with packed f32x2 FMAs -------------------------
__global__ void gemm4_kernel(const float* __restrict__ wkp,
                             const float* __restrict__ wqp,
                             const float* __restrict__ wvp,
                             const float* __restrict__ wsp) {
    extern __shared__ float sm[];
    float* As = sm;                // [128 rows][128 k]
    float* Bt = sm + 128 * 128;    // [64 cols][BPAD k]
    int t = threadIdx.x;
    int mat = blockIdx.x >> 1;
    int col0 = (blockIdx.x & 1) * 64;
    const float* W = (mat == 0) ? wkp : (mat == 1) ? wqp : (mat == 2) ? wvp : wsp;
    int row0 = blockIdx.y * 128;

    {
        int k4 = t & 31;
        int r0 = t >> 5;
#pragma unroll
        for (int rr = r0; rr < 128; rr += 8) {
            float4 val = make_float4(0.f, 0.f, 0.f, 0.f);
            int grow = row0 + rr;
            if (grow < NN) val = *(const float4*)(g_h + (size_t)grow * DD + k4 * 4);
            *(float4*)(As + rr * 128 + k4 * 4) = val;
        }
    }
    {
        int c = t & 63;
        int k0 = t >> 6;
#pragma unroll
        for (int kk = k0; kk < 128; kk += 4)
            Bt[c * BPAD + kk] = W[kk * DD + col0 + c];
    }
    __syncthreads();

    int ty = t >> 4, tx = t & 15;
    const float* arow = As + (ty * 8) * 128;

    u64 acc[8][4];
#pragma unroll
    for (int i = 0; i < 8; i++)
#pragma unroll
        for (int j = 0; j < 4; j++) acc[i][j] = 0ull;

#pragma unroll 4
    for (int kk = 0; kk < 128; kk += 4) {
        u64 b[4][2];
#pragma unroll
        for (int j = 0; j < 4; j++) {
            const u64* bp = (const u64*)(Bt + (tx + 16 * j) * BPAD + kk);
            b[j][0] = bp[0];
            b[j][1] = bp[1];
        }
#pragma unroll
        for (int i = 0; i < 8; i++) {
            const u64* ap = (const u64*)(arow + i * 128 + kk);
            u64 a0 = ap[0], a1 = ap[1];
#pragma unroll
            for (int j = 0; j < 4; j++) {
                ffma2(acc[i][j], a0, b[j][0]);
                ffma2(acc[i][j], a1, b[j][1]);
            }
        }
    }

    int crow0 = row0 + ty * 8;
    if (mat < 2) {
        __half* Oh = (mat == 0) ? g_kh : g_qh;
#pragma unroll
        for (int i = 0; i < 8; i++) {
            int grow = crow0 + i;
            if (grow < NN) {
                __half* orow = Oh + (size_t)grow * DD + col0 + tx;
#pragma unroll
                for (int j = 0; j < 4; j++)
                    orow[16 * j] = __float2half_rn(fold2(acc[i][j]));
            }
        }
    } else {
        float* O = (mat == 2) ? g_v : g_agg;
#pragma unroll
        for (int i = 0; i < 8; i++) {
            int grow = crow0 + i;
            if (grow < NN) {
                float* orow = O + (size_t)grow * DD + col0 + tx;
#pragma unroll
                for (int j = 0; j < 4; j++) orow[16 * j] = fold2(acc[i][j]);
            }
        }
    }
}

// ---------------- CSR aggregation: warp per dst node + fused BN stats --------
__global__ void agg_kernel(int stage) {
    __shared__ float ssum[DD], ssq[DD];
    int t = threadIdx.x;
    if (t < DD) {
        ssum[t] = 0.f;
        ssq[t] = 0.f;
    }
    __syncthreads();
    int lane = t & 31;
    int c0 = lane * 4;
    int gw = (blockIdx.x * blockDim.x + t) >> 5;
    int nwarps = (gridDim.x * blockDim.x) >> 5;
    float st[4] = {0.f, 0.f, 0.f, 0.f};
    float sq[4] = {0.f, 0.f, 0.f, 0.f};

    for (int n = gw; n < NN; n += nwarps) {
        int beg = __ldg(g_off + n);
        int end = __ldg(g_off + n + 1);
        uint2 kraw = __ldg((const uint2*)(g_kh + (size_t)n * DD + c0));
        float2 kf0 = __half22float2(*(__half2*)&kraw.x);
        float2 kf1 = __half22float2(*(__half2*)&kraw.y);
        float a0 = 0.f, a1 = 0.f, a2 = 0.f, a3 = 0.f;
        int e = beg;
        for (; e + 2 <= end; e += 2) {
            int s0 = __ldg(g_esrc + e);
            int s1 = __ldg(g_esrc + e + 1);
            uint2 q0r = __ldg((const uint2*)(g_qh + (size_t)s0 * DD + c0));
            float4 v0 = __ldg((const float4*)(g_v + (size_t)s0 * DD + c0));
            uint2 q1r = __ldg((const uint2*)(g_qh + (size_t)s1 * DD + c0));
            float4 v1 = __ldg((const float4*)(g_v + (size_t)s1 * DD + c0));
            float2 qa = __half22float2(*(__half2*)&q0r.x);
            float2 qb = __half22float2(*(__half2*)&q0r.y);
            a0 += v0.x / (1.f + __expf(-(kf0.x + qa.x)));
            a1 += v0.y / (1.f + __expf(-(kf0.y + qa.y)));
            a2 += v0.z / (1.f + __expf(-(kf1.x + qb.x)));
            a3 += v0.w / (1.f + __expf(-(kf1.y + qb.y)));
            float2 qc = __half22float2(*(__half2*)&q1r.x);
            float2 qd = __half22float2(*(__half2*)&q1r.y);
            a0 += v1.x / (1.f + __expf(-(kf0.x + qc.x)));
            a1 += v1.y / (1.f + __expf(-(kf0.y + qc.y)));
            a2 += v1.z / (1.f + __expf(-(kf1.x + qd.x)));
            a3 += v1.w / (1.f + __expf(-(kf1.y + qd.y)));
        }
        if (e < end) {
            int s0 = __ldg(g_esrc + e);
            uint2 q0r = __ldg((const uint2*)(g_qh + (size_t)s0 * DD + c0));
            float4 v0 = __ldg((const float4*)(g_v + (size_t)s0 * DD + c0));
            float2 qa = __half22float2(*(__half2*)&q0r.x);
            float2 qb = __half22float2(*(__half2*)&q0r.y);
            a0 += v0.x / (1.f + __expf(-(kf0.x + qa.x)));
            a1 += v0.y / (1.f + __expf(-(kf0.y + qa.y)));
            a2 += v0.z / (1.f + __expf(-(kf1.x + qb.x)));
            a3 += v0.w / (1.f + __expf(-(kf1.y + qb.y)));
        }
        float* ap = g_agg + (size_t)n * DD + c0;
        float4 skip = *(const float4*)ap;
        float o0 = skip.x + a0, o1 = skip.y + a1, o2 = skip.z + a2, o3 = skip.w + a3;
        *(float4*)ap = make_float4(o0, o1, o2, o3);
        st[0] += o0; st[1] += o1; st[2] += o2; st[3] += o3;
        sq[0] += o0 * o0; sq[1] += o1 * o1; sq[2] += o2 * o2; sq[3] += o3 * o3;
    }
#pragma unroll
    for (int j = 0; j < 4; j++) {
        atomicAdd(&ssum[c0 + j], st[j]);
        atomicAdd(&ssq[c0 + j], sq[j]);
    }
    __syncthreads();
    if (t < DD) {
        atomicAdd(&g_sum[stage * DD + t], ssum[t]);
        atomicAdd(&g_sumsq[stage * DD + t], ssq[t]);
    }
}

// ---------------- launch ----------------------------------------------------
extern "C" void kernel_launch(void* const* d_in, const int* in_sizes, int n_in,
                              void* d_out, int out_size) {
    const float* x     = (const float*)d_in[0];
    const int*   ei    = (const int*)d_in[1];
    const float* pre_w = (const float*)d_in[2];
    const float* pre_g = (const float*)d_in[3];
    const float* pre_b = (const float*)d_in[4];
    const float* wk    = (const float*)d_in[5];
    const float* wq    = (const float*)d_in[6];
    const float* wv    = (const float*)d_in[7];
    const float* ws    = (const float*)d_in[8];
    const float* mg    = (const float*)d_in[9];
    const float* mb    = (const float*)d_in[10];
    float* outp = (float*)d_out;

    cudaFuncSetAttribute(gemm4_kernel,
                         cudaFuncAttributeMaxDynamicSharedMemorySize,
                         (int)GEMM_SMEM);

    init_kernel<<<(NN + 256) / 256, 256>>>();
    detect_kernel<<<256, 256>>>((const unsigned int*)ei);
    convert_kernel<<<(EE + 255) / 256, 256>>>(ei);
    scan1_kernel<<<SB, 256>>>();
    scan2_kernel<<<1, SB>>>();
    scan3_kernel<<<SB, 256>>>();
    scatter_kernel<<<(EE + 255) / 256, 256>>>();

    // pre-MP: linear (+ fused BN stats) -> BN -> ReLU -> l2norm
    pre_linear_kernel<<<(NN + PL_ROWS - 1) / PL_ROWS, 256>>>(x, pre_w);
    bn_apply_kernel<<<(NN + 7) / 8, 256>>>(0, 0, pre_g, pre_b, nullptr);

    const int gemm_gy = (NN + 127) / 128;
    for (int l = 0; l < 2; l++) {
        gemm4_kernel<<<dim3(8, gemm_gy), 256, GEMM_SMEM>>>(
            wk + l * DD * DD, wq + l * DD * DD, wv + l * DD * DD, ws + l * DD * DD);
        agg_kernel<<<1184, 256>>>(1 + l);
        bn_apply_kernel<<<(NN + 7) / 8, 256>>>(
            1, 1 + l, mg + l * DD, mb + l * DD, (l == 1) ? outp : nullptr);
    }
}

// round 6
// speedup vs baseline: 2.4982x; 1.3910x over previous
#include <cuda_runtime.h>
#include <cuda_fp16.h>
#include <math.h>

#define NN 50000
#define EE 800000
#define DIN 20
#define DD 128
#define BN_EPS 1e-5f

#define SB 64          // scan blocks
#define CHUNK 800      // nodes per scan block
#define PT 4           // nodes per scan thread

#define TPAD 132
#define TC_SMEM (size_t)(2 * 128 * TPAD * sizeof(float))

typedef unsigned long long u64;
typedef unsigned int u32;

// ---------------- scratch (device globals; no runtime allocation) ----------
__device__ float g_h[NN * DD];
__device__ __half g_kh[NN * DD];
__device__ __half g_qh[NN * DD];
__device__ float g_v[NN * DD];
__device__ float g_agg[NN * DD];
__device__ float g_sum[3 * DD], g_sumsq[3 * DD];
__device__ int g_src[EE], g_dst[EE];
__device__ int g_deg[NN + 1];
__device__ int g_off[NN + 1];
__device__ int g_pos[NN];
__device__ int g_esrc[EE];
__device__ int g_bsum[SB], g_bpre[SB];
__device__ unsigned int g_or;

// ---------------- tf32 helper ------------------------------------------------
__device__ __forceinline__ float tf32r(float x) {
    u32 u;
    asm("cvt.rna.tf32.f32 %0, %1;" : "=r"(u) : "f"(x));
    return __uint_as_float(u);
}

// ---------------- init --------------------------------------------------------
__global__ void init_kernel() {
    int i = blockIdx.x * blockDim.x + threadIdx.x;
    if (i == 0) g_or = 0u;
    if (i < 3 * DD) {
        g_sum[i] = 0.f;
        g_sumsq[i] = 0.f;
    }
    if (i <= NN) g_deg[i] = 0;
}

__global__ void detect_kernel(const unsigned int* __restrict__ w) {
    unsigned int v = 0;
    for (long long i = blockIdx.x * (long long)blockDim.x + threadIdx.x;
         i < EE; i += (long long)gridDim.x * blockDim.x)
        v |= w[2 * i + 1];
#pragma unroll
    for (int o = 16; o > 0; o >>= 1) v |= __shfl_xor_sync(0xffffffffu, v, o);
    if ((threadIdx.x & 31) == 0 && v) atomicOr(&g_or, v);
}

__global__ void convert_kernel(const int* __restrict__ ei) {
    int i = blockIdx.x * blockDim.x + threadIdx.x;
    if (i >= EE) return;
    int s, d;
    if (g_or == 0u) {
        const long long* e64 = (const long long*)ei;
        s = (int)e64[i];
        d = (int)e64[EE + i];
    } else {
        s = ei[i];
        d = ei[EE + i];
    }
    g_src[i] = s;
    g_dst[i] = d;
    atomicAdd(&g_deg[d], 1);
}

// ---------------- exclusive scan (3 kernels) ----------------------------------
__global__ void scan1_kernel() {
    __shared__ int sh[256];
    int b = blockIdx.x, t = threadIdx.x;
    int base = b * CHUNK + t * PT;
    int s = 0;
#pragma unroll
    for (int j = 0; j < PT; j++) {
        int idx = base + j;
        if (idx < b * CHUNK + CHUNK && idx < NN) s += g_deg[idx];
    }
    sh[t] = s;
    __syncthreads();
    for (int o = 128; o > 0; o >>= 1) {
        if (t < o) sh[t] += sh[t + o];
        __syncthreads();
    }
    if (t == 0) g_bsum[b] = sh[0];
}

__global__ void scan2_kernel() {
    __shared__ int sh[SB];
    int t = threadIdx.x;
    sh[t] = g_bsum[t];
    __syncthreads();
    if (t == 0) {
        int run = 0;
        for (int i = 0; i < SB; i++) {
            int v = sh[i];
            sh[i] = run;
            run += v;
        }
    }
    __syncthreads();
    g_bpre[t] = sh[t];
}

__global__ void scan3_kernel() {
    __shared__ int arr[256];
    int b = blockIdx.x, t = threadIdx.x;
    int base = b * CHUNK + t * PT;
    int dv[PT];
    int tsum = 0;
#pragma unroll
    for (int j = 0; j < PT; j++) {
        int idx = base + j;
        dv[j] = (idx < b * CHUNK + CHUNK && idx < NN) ? g_deg[idx] : 0;
        tsum += dv[j];
    }
    arr[t] = tsum;
    __syncthreads();
#pragma unroll
    for (int o = 1; o < 256; o <<= 1) {
        int v = (t >= o) ? arr[t - o] : 0;
        __syncthreads();
        arr[t] += v;
        __syncthreads();
    }
    int run = g_bpre[b] + arr[t] - tsum;
#pragma unroll
    for (int j = 0; j < PT; j++) {
        int idx = base + j;
        if (idx < b * CHUNK + CHUNK && idx < NN) {
            g_off[idx] = run;
            g_pos[idx] = run;
            run += dv[j];
        }
    }
    if (b == 0 && t == 0) g_off[NN] = EE;
}

__global__ void scatter_kernel() {
    int i = blockIdx.x * blockDim.x + threadIdx.x;
    if (i >= EE) return;
    int d = g_dst[i];
    int p = atomicAdd(&g_pos[d], 1);
    g_esrc[p] = g_src[i];
}

// ---------------- pre-MP linear + fused stage-0 BN stats ----------------------
#define PL_ROWS 32
__global__ void pre_linear_kernel(const float* __restrict__ x,
                                  const float* __restrict__ w) {
    __shared__ float xs[PL_ROWS][DIN];
    __shared__ float ssum[DD], ssq[DD];
    int t = threadIdx.x;
    int c = t & 127;
    int rl = t >> 7;
    float wr[DIN];
#pragma unroll
    for (int kk = 0; kk < DIN; kk++) wr[kk] = w[kk * DD + c];
    if (t < DD) {
        ssum[t] = 0.f;
        ssq[t] = 0.f;
    }
    int row0 = blockIdx.x * PL_ROWS;
    for (int i = t; i < PL_ROWS * DIN; i += 256) {
        int rr = i / DIN, kk = i % DIN;
        int grow = row0 + rr;
        xs[rr][kk] = (grow < NN) ? x[(size_t)grow * DIN + kk] : 0.f;
    }
    __syncthreads();
    float s = 0.f, s2 = 0.f;
#pragma unroll 4
    for (int r2 = 0; r2 < PL_ROWS; r2 += 2) {
        int r = r2 + rl;
        int grow = row0 + r;
        float acc = 0.f;
#pragma unroll
        for (int kk = 0; kk < DIN; kk++) acc += xs[r][kk] * wr[kk];
        if (grow < NN) {
            g_h[(size_t)grow * DD + c] = acc;
            s += acc;
            s2 += acc * acc;
        }
    }
    atomicAdd(&ssum[c], s);
    atomicAdd(&ssq[c], s2);
    __syncthreads();
    if (t < DD) {
        atomicAdd(&g_sum[t], ssum[t]);
        atomicAdd(&g_sumsq[t], ssq[t]);
    }
}

// ---------------- fused BN finalize -> BN -> ReLU -> l2norm --------------------
__global__ void bn_apply_kernel(int which, int stage,
                                const float* __restrict__ gamma,
                                const float* __restrict__ beta,
                                float* __restrict__ out_ext) {
    __shared__ float smu[DD], srs[DD];
    int t = threadIdx.x;
    if (t < DD) {
        float mu = g_sum[stage * DD + t] * (1.f / NN);
        float var = g_sumsq[stage * DD + t] * (1.f / NN) - mu * mu;
        smu[t] = mu;
        srs[t] = rsqrtf(var + BN_EPS) * gamma[t];
    }
    __syncthreads();
    const float* xp = which ? g_agg : g_h;
    int gt = blockIdx.x * blockDim.x + t;
    int row = gt >> 5;
    int lane = gt & 31;
    if (row >= NN) return;
    int c0 = lane * 4;
    float4 xv = *(const float4*)(xp + (size_t)row * DD + c0);
    float xsv[4] = {xv.x, xv.y, xv.z, xv.w};
    float y[4];
    float ss = 0.f;
#pragma unroll
    for (int j = 0; j < 4; j++) {
        int c = c0 + j;
        float val = (xsv[j] - smu[c]) * srs[c] + beta[c];
        val = fmaxf(val, 0.f);
        y[j] = val;
        ss += val * val;
    }
#pragma unroll
    for (int o = 16; o > 0; o >>= 1) ss += __shfl_xor_sync(0xffffffffu, ss, o);
    float sc = 1.f / fmaxf(sqrtf(ss), 1e-12f);
    float* op = out_ext ? out_ext : g_h;
    float4 ov = make_float4(y[0] * sc, y[1] * sc, y[2] * sc, y[3] * sc);
    *(float4*)(op + (size_t)row * DD + c0) = ov;
}

// ---------------- tensor-core GEMM: tf32 mma.sync, 128x128 tile --------------
// grid (4, ceil(NN/128)); blockIdx.x = matrix {k,q,v,skip}. 256 thr = 8 warps
// (2 m-groups x 4 n-groups); warp tile 64x32; K=128, 16 k-steps of k8.
__global__ void gemm_tc_kernel(const float* __restrict__ wkp,
                               const float* __restrict__ wqp,
                               const float* __restrict__ wvp,
                               const float* __restrict__ wsp) {
    extern __shared__ float sm[];
    float* As = sm;               // [128][TPAD] row-major (row, k)
    float* Bs = sm + 128 * TPAD;  // [128][TPAD] k-major (k, n)
    int t = threadIdx.x;
    int mat = blockIdx.x;
    const float* W = (mat == 0) ? wkp : (mat == 1) ? wqp : (mat == 2) ? wvp : wsp;
    int row0 = blockIdx.y * 128;

    // Load + tf32-truncate A tile (h rows) and B tile (weights).
#pragma unroll
    for (int i = 0; i < 16; i++) {
        int idx = t + 256 * i;
        int r = idx >> 5, c4 = (idx & 31) * 4;
        float4 v = make_float4(0.f, 0.f, 0.f, 0.f);
        int grow = row0 + r;
        if (grow < NN) v = *(const float4*)(g_h + (size_t)grow * DD + c4);
        float* dst = As + r * TPAD + c4;
        ((float2*)dst)[0] = make_float2(tf32r(v.x), tf32r(v.y));
        ((float2*)(dst + 2))[0] = make_float2(tf32r(v.z), tf32r(v.w));
    }
#pragma unroll
    for (int i = 0; i < 16; i++) {
        int idx = t + 256 * i;
        int k = idx >> 5, c4 = (idx & 31) * 4;
        float4 v = *(const float4*)(W + k * DD + c4);
        float* dst = Bs + k * TPAD + c4;
        ((float2*)dst)[0] = make_float2(tf32r(v.x), tf32r(v.y));
        ((float2*)(dst + 2))[0] = make_float2(tf32r(v.z), tf32r(v.w));
    }
    __syncthreads();

    int lane = t & 31, wid = t >> 5;
    int gid = lane >> 2, tig = lane & 3;
    int wm = wid >> 2, wn = wid & 3;

    float c[4][4][4];
#pragma unroll
    for (int mi = 0; mi < 4; mi++)
#pragma unroll
        for (int nj = 0; nj < 4; nj++)
#pragma unroll
            for (int r = 0; r < 4; r++) c[mi][nj][r] = 0.f;

    const float* Ab = As + (wm * 64 + gid) * TPAD + tig;
    const float* Bb = Bs + tig * TPAD + wn * 32 + gid;

#pragma unroll
    for (int ks = 0; ks < 16; ks++) {
        int k0 = ks * 8;
        u32 a[4][4];
#pragma unroll
        for (int mi = 0; mi < 4; mi++) {
            const float* p = Ab + mi * 16 * TPAD + k0;
            a[mi][0] = __float_as_uint(p[0]);
            a[mi][1] = __float_as_uint(p[8 * TPAD]);
            a[mi][2] = __float_as_uint(p[4]);
            a[mi][3] = __float_as_uint(p[8 * TPAD + 4]);
        }
        u32 b[4][2];
#pragma unroll
        for (int nj = 0; nj < 4; nj++) {
            const float* p = Bb + k0 * TPAD + nj * 8;
            b[nj][0] = __float_as_uint(p[0]);
            b[nj][1] = __float_as_uint(p[4 * TPAD]);
        }
#pragma unroll
        for (int mi = 0; mi < 4; mi++)
#pragma unroll
            for (int nj = 0; nj < 4; nj++) {
                asm volatile(
                    "mma.sync.aligned.m16n8k8.row.col.f32.tf32.tf32.f32 "
                    "{%0,%1,%2,%3}, {%4,%5,%6,%7}, {%8,%9}, {%0,%1,%2,%3};"
                    : "+f"(c[mi][nj][0]), "+f"(c[mi][nj][1]),
                      "+f"(c[mi][nj][2]), "+f"(c[mi][nj][3])
                    : "r"(a[mi][0]), "r"(a[mi][1]), "r"(a[mi][2]), "r"(a[mi][3]),
                      "r"(b[nj][0]), "r"(b[nj][1]));
            }
    }

    // Epilogue: c0,c1 -> row (base), c2,c3 -> row+8; cols = wn*32+nj*8+2*tig.
    int orow = row0 + wm * 64 + gid;
    if (mat < 2) {
        __half* O = (mat == 0) ? g_kh : g_qh;
#pragma unroll
        for (int mi = 0; mi < 4; mi++) {
            int r0 = orow + mi * 16;
#pragma unroll
            for (int nj = 0; nj < 4; nj++) {
                int col = wn * 32 + nj * 8 + 2 * tig;
                if (r0 < NN)
                    *(__half2*)(O + (size_t)r0 * DD + col) =
                        __floats2half2_rn(c[mi][nj][0], c[mi][nj][1]);
                if (r0 + 8 < NN)
                    *(__half2*)(O + (size_t)(r0 + 8) * DD + col) =
                        __floats2half2_rn(c[mi][nj][2], c[mi][nj][3]);
            }
        }
    } else {
        float* O = (mat == 2) ? g_v : g_agg;
#pragma unroll
        for (int mi = 0; mi < 4; mi++) {
            int r0 = orow + mi * 16;
#pragma unroll
            for (int nj = 0; nj < 4; nj++) {
                int col = wn * 32 + nj * 8 + 2 * tig;
                if (r0 < NN)
                    *(float2*)(O + (size_t)r0 * DD + col) =
                        make_float2(c[mi][nj][0], c[mi][nj][1]);
                if (r0 + 8 < NN)
                    *(float2*)(O + (size_t)(r0 + 8) * DD + col) =
                        make_float2(c[mi][nj][2], c[mi][nj][3]);
            }
        }
    }
}

// ---------------- CSR aggregation: warp per dst node + fused BN stats ---------
__global__ void agg_kernel(int stage) {
    __shared__ float ssum[DD], ssq[DD];
    int t = threadIdx.x;
    if (t < DD) {
        ssum[t] = 0.f;
        ssq[t] = 0.f;
    }
    __syncthreads();
    int lane = t & 31;
    int c0 = lane * 4;
    int gw = (blockIdx.x * blockDim.x + t) >> 5;
    int nwarps = (gridDim.x * blockDim.x) >> 5;
    float st[4] = {0.f, 0.f, 0.f, 0.f};
    float sq[4] = {0.f, 0.f, 0.f, 0.f};

    for (int n = gw; n < NN; n += nwarps) {
        int beg = __ldg(g_off + n);
        int end = __ldg(g_off + n + 1);
        uint2 kraw = __ldg((const uint2*)(g_kh + (size_t)n * DD + c0));
        float2 kf0 = __half22float2(*(__half2*)&kraw.x);
        float2 kf1 = __half22float2(*(__half2*)&kraw.y);
        float a0 = 0.f, a1 = 0.f, a2 = 0.f, a3 = 0.f;
        int e = beg;
        for (; e + 2 <= end; e += 2) {
            int s0 = __ldg(g_esrc + e);
            int s1 = __ldg(g_esrc + e + 1);
            uint2 q0r = __ldg((const uint2*)(g_qh + (size_t)s0 * DD + c0));
            float4 v0 = __ldg((const float4*)(g_v + (size_t)s0 * DD + c0));
            uint2 q1r = __ldg((const uint2*)(g_qh + (size_t)s1 * DD + c0));
            float4 v1 = __ldg((const float4*)(g_v + (size_t)s1 * DD + c0));
            float2 qa = __half22float2(*(__half2*)&q0r.x);
            float2 qb = __half22float2(*(__half2*)&q0r.y);
            a0 += v0.x / (1.f + __expf(-(kf0.x + qa.x)));
            a1 += v0.y / (1.f + __expf(-(kf0.y + qa.y)));
            a2 += v0.z / (1.f + __expf(-(kf1.x + qb.x)));
            a3 += v0.w / (1.f + __expf(-(kf1.y + qb.y)));
            float2 qc = __half22float2(*(__half2*)&q1r.x);
            float2 qd = __half22float2(*(__half2*)&q1r.y);
            a0 += v1.x / (1.f + __expf(-(kf0.x + qc.x)));
            a1 += v1.y / (1.f + __expf(-(kf0.y + qc.y)));
            a2 += v1.z / (1.f + __expf(-(kf1.x + qd.x)));
            a3 += v1.w / (1.f + __expf(-(kf1.y + qd.y)));
        }
        if (e < end) {
            int s0 = __ldg(g_esrc + e);
            uint2 q0r = __ldg((const uint2*)(g_qh + (size_t)s0 * DD + c0));
            float4 v0 = __ldg((const float4*)(g_v + (size_t)s0 * DD + c0));
            float2 qa = __half22float2(*(__half2*)&q0r.x);
            float2 qb = __half22float2(*(__half2*)&q0r.y);
            a0 += v0.x / (1.f + __expf(-(kf0.x + qa.x)));
            a1 += v0.y / (1.f + __expf(-(kf0.y + qa.y)));
            a2 += v0.z / (1.f + __expf(-(kf1.x + qb.x)));
            a3 += v0.w / (1.f + __expf(-(kf1.y + qb.y)));
        }
        float* ap = g_agg + (size_t)n * DD + c0;
        float4 skip = *(const float4*)ap;
        float o0 = skip.x + a0, o1 = skip.y + a1, o2 = skip.z + a2, o3 = skip.w + a3;
        *(float4*)ap = make_float4(o0, o1, o2, o3);
        st[0] += o0; st[1] += o1; st[2] += o2; st[3] += o3;
        sq[0] += o0 * o0; sq[1] += o1 * o1; sq[2] += o2 * o2; sq[3] += o3 * o3;
    }
#pragma unroll
    for (int j = 0; j < 4; j++) {
        atomicAdd(&ssum[c0 + j], st[j]);
        atomicAdd(&ssq[c0 + j], sq[j]);
    }
    __syncthreads();
    if (t < DD) {
        atomicAdd(&g_sum[stage * DD + t], ssum[t]);
        atomicAdd(&g_sumsq[stage * DD + t], ssq[t]);
    }
}

// ---------------- launch -------------------------------------------------------
extern "C" void kernel_launch(void* const* d_in, const int* in_sizes, int n_in,
                              void* d_out, int out_size) {
    const float* x     = (const float*)d_in[0];
    const int*   ei    = (const int*)d_in[1];
    const float* pre_w = (const float*)d_in[2];
    const float* pre_g = (const float*)d_in[3];
    const float* pre_b = (const float*)d_in[4];
    const float* wk    = (const float*)d_in[5];
    const float* wq    = (const float*)d_in[6];
    const float* wv    = (const float*)d_in[7];
    const float* ws    = (const float*)d_in[8];
    const float* mg    = (const float*)d_in[9];
    const float* mb    = (const float*)d_in[10];
    float* outp = (float*)d_out;

    cudaFuncSetAttribute(gemm_tc_kernel,
                         cudaFuncAttributeMaxDynamicSharedMemorySize,
                         (int)TC_SMEM);

    init_kernel<<<(NN + 256) / 256, 256>>>();
    detect_kernel<<<256, 256>>>((const unsigned int*)ei);
    convert_kernel<<<(EE + 255) / 256, 256>>>(ei);
    scan1_kernel<<<SB, 256>>>();
    scan2_kernel<<<1, SB>>>();
    scan3_kernel<<<SB, 256>>>();
    scatter_kernel<<<(EE + 255) / 256, 256>>>();

    pre_linear_kernel<<<(NN + PL_ROWS - 1) / PL_ROWS, 256>>>(x, pre_w);
    bn_apply_kernel<<<(NN + 7) / 8, 256>>>(0, 0, pre_g, pre_b, nullptr);

    const int gemm_gy = (NN + 127) / 128;
    for (int l = 0; l < 2; l++) {
        gemm_tc_kernel<<<dim3(4, gemm_gy), 256, TC_SMEM>>>(
            wk + l * DD * DD, wq + l * DD * DD, wv + l * DD * DD, ws + l * DD * DD);
        agg_kernel<<<1184, 256>>>(1 + l);
        bn_apply_kernel<<<(NN + 7) / 8, 256>>>(
            1, 1 + l, mg + l * DD, mb + l * DD, (l == 1) ? outp : nullptr);
    }
}